// round 6
// baseline (speedup 1.0000x reference)
#include <cuda_runtime.h>
#include <cuda_bf16.h>
#include <math.h>

// Problem constants
#define NB   64     // batch
#define TT   512    // time steps
#define DD   512    // input dim
#define HH   512    // hidden dim
#define G4   2048   // 4*H

typedef unsigned long long u64;

// ---------------------------------------------------------------------------
// Packed f32x2 helpers (sm_103a FFMA2 — ptxas never auto-generates these)
// ---------------------------------------------------------------------------
__device__ __forceinline__ u64 pack_dup(float v)
{
    u64 r; asm("mov.b64 %0, {%1, %1};" : "=l"(r) : "f"(v)); return r;
}
__device__ __forceinline__ void ffma2(u64& acc, u64 a, u64 b)
{
    asm("fma.rn.f32x2 %0, %1, %2, %0;" : "+l"(acc) : "l"(a), "l"(b));
}
__device__ __forceinline__ float2 unpk(u64 v)
{
    float2 r; asm("mov.b64 {%0, %1}, %2;" : "=f"(r.x), "=f"(r.y) : "l"(v)); return r;
}

// ---------------------------------------------------------------------------
// Scratch (device globals: the sanctioned no-alloc workaround)
// ---------------------------------------------------------------------------
#define NCTA 128
#define FLAG_STRIDE 32   // 128B between flags -> distinct L2 lines/slices

__device__ float    g_xh[(size_t)TT * NB * G4];   // (T, N, 4H) pre-projected gates
__device__ unsigned g_flag[NCTA * FLAG_STRIDE];   // per-CTA step flags, padded

// ---------------------------------------------------------------------------
// Kernel 1: xh = x @ W_xh + (b_xh + b_hh)   — FFMA2 inner loop (unchanged)
// ---------------------------------------------------------------------------
#define BM 128
#define BN 128
#define BK 8

__global__ __launch_bounds__(256, 2)
void gemm_xh_kernel(const float* __restrict__ x,
                    const float* __restrict__ Wxh,
                    const float* __restrict__ bxh,
                    const float* __restrict__ bhh)
{
    __shared__ float As[BK][BM];   // transposed A tile
    __shared__ float Bs[BK][BN];

    const int tid = threadIdx.x;
    const int bm  = blockIdx.y;
    const int bn  = blockIdx.x;

    const int warp = tid >> 5, lane = tid & 31;
    const int wm = warp >> 1, wn = warp & 1;
    const int tm = lane & 3,  tn = lane >> 2;
    const int m0 = wm * 32 + tm * 8;
    const int n0 = wn * 64 + tn * 8;

    const int ar = tid >> 1;
    const int aq = tid & 1;
    const int gm = bm * BM + ar;            // global row m = t*64+n
    const int t  = gm >> 6;
    const int nn = gm & 63;
    const float* __restrict__ arow = x + ((size_t)nn * TT + t) * DD;

    const int rb = tid >> 5;
    const int cb = (tid & 31) * 4;
    const float* __restrict__ bcol = Wxh + (size_t)bn * BN + cb;

    u64 acc2[8][4];
#pragma unroll
    for (int i = 0; i < 8; i++)
#pragma unroll
        for (int j = 0; j < 4; j++) acc2[i][j] = 0ull;

    for (int k0 = 0; k0 < DD; k0 += BK) {
        const float4 av = *(const float4*)(arow + k0 + aq * 4);
        const float4 bv = *(const float4*)(bcol + (size_t)(k0 + rb) * G4);
        __syncthreads();
        As[aq * 4 + 0][ar] = av.x;
        As[aq * 4 + 1][ar] = av.y;
        As[aq * 4 + 2][ar] = av.z;
        As[aq * 4 + 3][ar] = av.w;
        *(float4*)&Bs[rb][cb] = bv;
        __syncthreads();

#pragma unroll
        for (int kk = 0; kk < BK; kk++) {
            float ra[8];
            *(float4*)&ra[0] = *(const float4*)&As[kk][m0];
            *(float4*)&ra[4] = *(const float4*)&As[kk][m0 + 4];
            const ulonglong2 b01 = *(const ulonglong2*)&Bs[kk][n0];
            const ulonglong2 b23 = *(const ulonglong2*)&Bs[kk][n0 + 4];
#pragma unroll
            for (int i = 0; i < 8; i++) {
                const u64 ai = pack_dup(ra[i]);
                ffma2(acc2[i][0], ai, b01.x);
                ffma2(acc2[i][1], ai, b01.y);
                ffma2(acc2[i][2], ai, b23.x);
                ffma2(acc2[i][3], ai, b23.y);
            }
        }
    }

    const int col0 = bn * BN + n0;
    float bsum[8];
#pragma unroll
    for (int j = 0; j < 8; j++)
        bsum[j] = bxh[col0 + j] + bhh[col0 + j];

#pragma unroll
    for (int i = 0; i < 8; i++) {
        const size_t row = (size_t)(bm * BM + m0 + i);
        float* p = g_xh + row * G4 + col0;
        float2 c0 = unpk(acc2[i][0]);
        float2 c1 = unpk(acc2[i][1]);
        float2 c2 = unpk(acc2[i][2]);
        float2 c3 = unpk(acc2[i][3]);
        float4 v0 = make_float4(c0.x + bsum[0], c0.y + bsum[1],
                                c1.x + bsum[2], c1.y + bsum[3]);
        float4 v1 = make_float4(c2.x + bsum[4], c2.y + bsum[5],
                                c3.x + bsum[6], c3.y + bsum[7]);
        *(float4*)p       = v0;
        *(float4*)(p + 4) = v1;
    }
}

// ---------------------------------------------------------------------------
// Kernel 2: flag reset (runs each launch before the LSTM kernel,
// keeping graph replays deterministic)
// ---------------------------------------------------------------------------
__global__ void reset_bar_kernel()
{
    const int i = blockIdx.x * blockDim.x + threadIdx.x;
    if (i < NCTA * FLAG_STRIDE) g_flag[i] = 0u;
}

// ---------------------------------------------------------------------------
// Kernel 3: persistent LSTM recurrence.
// NEW vs R5:
//  * Distributed flag barrier: CTA b releases st.release.gpu flag[b]=t+1
//    (own 128B-padded slot -> NO per-address atomic serialization, which cost
//    ~128*27 cyc/step with the old single-counter red.add). Threads 0..127
//    each poll one flag in parallel with ld.acquire.gpu; __syncthreads chains
//    the acquire CTA-wide (same happens-before shape as CG grid.sync).
//  * g_xh gate vector prefetched at the TOP of the step (independent of other
//    CTAs) instead of after the dot loop, hiding its ~600cyc L2 latency.
// Unchanged: smem-staged h (coalesced), smem W_hh (k-contiguous FFMA2 pairs),
// c state in registers.
// ---------------------------------------------------------------------------
#define CPC  4            // hidden cols per CTA
#define WS_STRIDE 2052    // 4*512 + 4 floats per cg slice (bank-shift pad)
#define HS_STRIDE 516     // 512 + 4 floats per h row (bank-shift pad)
#define HS_BYTES  (NB * HS_STRIDE * 4)   // 132096

__device__ __forceinline__ float sigmoidf_(float v)
{
    return 1.f / (1.f + expf(-v));
}

__global__ __launch_bounds__(256, 1)
void lstm_kernel(const float* __restrict__ Whh, float* __restrict__ y)
{
    extern __shared__ float hs[];          // [NB][HS_STRIDE] staged h(t-1)
    __shared__ float wsT[4 * WS_STRIDE];   // ~32.8 KB
    __shared__ float gs[NB][17];           // gate staging, padded

    const int tid  = threadIdx.x;
    const int b    = blockIdx.x;
    const int jh0  = b * CPC;
    const int n    = tid >> 2;             // 0..63
    const int cg   = tid & 3;              // gate type: 0=i 1=f 2=g 3=o
    const int warp = tid >> 5;
    const int lane = tid & 31;

    // load + transpose W_hh slice into smem once
    for (int i = tid; i < 4 * 4 * HH; i += 256) {
        const int k = i & (HH - 1);
        const int j = (i >> 9) & 3;
        const int g = i >> 11;
        wsT[g * WS_STRIDE + j * HH + k] =
            Whh[(size_t)k * G4 + (size_t)g * HH + jh0 + j];
    }

    const float* __restrict__ wbase = &wsT[cg * WS_STRIDE];
    const float* __restrict__ hrow  = &hs[n * HS_STRIDE];

    const int n2 = tid >> 2;               // activation-phase mapping
    const int j2 = tid & 3;
    float creg = 0.f;                      // c state for (n2, jh0+j2)

    unsigned* const myflag   = &g_flag[b * FLAG_STRIDE];
    unsigned* const pollflag = &g_flag[(tid & (NCTA - 1)) * FLAG_STRIDE];

    __syncthreads();

    for (int tstep = 0; tstep < TT; tstep++) {
        // ---- prefetch this step's input-projection gates (no cross-CTA dep)
        const float4 xv = *(const float4*)(g_xh +
            ((size_t)tstep * NB + n) * G4 + (size_t)cg * HH + jh0);

        if (tstep > 0) {
            // ---- distributed barrier wait: all CTAs finished step tstep-1
            if (tid < NCTA) {
                const unsigned want = (unsigned)tstep;
                unsigned v;
                do {
                    asm volatile("ld.acquire.gpu.u32 %0, [%1];"
                                 : "=r"(v) : "l"(pollflag) : "memory");
                } while (v < want);
            }
            __syncthreads();

            // ---- stage h(t-1) into smem, coalesced: warp w copies rows w, w+8, ...
            const size_t tb = (size_t)(tstep - 1) * HH;
#pragma unroll
            for (int r8 = 0; r8 < 8; r8++) {
                const int row = warp + r8 * 8;
                const float4* __restrict__ src =
                    (const float4*)(y + (size_t)row * TT * HH + tb);
                float4* __restrict__ dst = (float4*)&hs[row * HS_STRIDE];
#pragma unroll
                for (int p = 0; p < 4; p++)
                    dst[lane + p * 32] = src[lane + p * 32];
            }
        }
        __syncthreads();

        // ---- dot: gates for (n, cg, cols jh0..jh0+3) from smem h and smem W
        u64 acc0 = 0ull, acc1 = 0ull, acc2v = 0ull, acc3 = 0ull;
        if (tstep > 0) {
#pragma unroll 8
            for (int k = 0; k < HH; k += 4) {
                const ulonglong2 hp = *(const ulonglong2*)(hrow + k);
                const ulonglong2 w0 = *(const ulonglong2*)(wbase + 0 * HH + k);
                const ulonglong2 w1 = *(const ulonglong2*)(wbase + 1 * HH + k);
                const ulonglong2 w2 = *(const ulonglong2*)(wbase + 2 * HH + k);
                const ulonglong2 w3 = *(const ulonglong2*)(wbase + 3 * HH + k);
                ffma2(acc0, hp.x, w0.x); ffma2(acc0, hp.y, w0.y);
                ffma2(acc1, hp.x, w1.x); ffma2(acc1, hp.y, w1.y);
                ffma2(acc2v, hp.x, w2.x); ffma2(acc2v, hp.y, w2.y);
                ffma2(acc3, hp.x, w3.x); ffma2(acc3, hp.y, w3.y);
            }
        }

        // horizontal reduce + prefetched input gates (biases folded in)
        float a0, a1, a2, a3;
        {
            const float2 s0 = unpk(acc0), s1 = unpk(acc1);
            const float2 s2 = unpk(acc2v), s3 = unpk(acc3);
            a0 = s0.x + s0.y + xv.x;
            a1 = s1.x + s1.y + xv.y;
            a2 = s2.x + s2.y + xv.z;
            a3 = s3.x + s3.y + xv.w;
        }

        gs[n][cg * 4 + 0] = a0;
        gs[n][cg * 4 + 1] = a1;
        gs[n][cg * 4 + 2] = a2;
        gs[n][cg * 4 + 3] = a3;
        __syncthreads();

        // ---- activations: one output column per thread
        {
            const float gi = gs[n2][0  + j2];
            const float gf = gs[n2][4  + j2];
            const float gc = gs[n2][8  + j2];
            const float go = gs[n2][12 + j2];
            const float iv = sigmoidf_(gi);
            const float fv = sigmoidf_(gf);
            const float gv = tanhf(gc);
            const float ov = sigmoidf_(go);
            creg = fv * creg + iv * gv;
            const float hv = ov * tanhf(creg);
            y[(size_t)n2 * TT * HH + (size_t)tstep * HH + jh0 + j2] = hv;
        }
        __syncthreads();   // all y stores done before the release below

        if (tstep < TT - 1) {
            // ---- distributed barrier arrive: one release store, own slot
            if (tid == 0) {
                asm volatile("st.release.gpu.u32 [%0], %1;"
                             :: "l"(myflag), "r"((unsigned)(tstep + 1))
                             : "memory");
            }
        }
    }
}

// ---------------------------------------------------------------------------
// Launch
// ---------------------------------------------------------------------------
extern "C" void kernel_launch(void* const* d_in, const int* in_sizes, int n_in,
                              void* d_out, int out_size)
{
    const float* x   = (const float*)d_in[0];   // (64, 512, 512)
    const float* Wxh = (const float*)d_in[1];   // (512, 2048)
    const float* Whh = (const float*)d_in[2];   // (512, 2048)
    const float* bxh = (const float*)d_in[3];   // (2048,)
    const float* bhh = (const float*)d_in[4];   // (2048,)
    float* y = (float*)d_out;                   // (64, 512, 512)

    // opt-in to >48KB dynamic smem (idempotent host call, capture-safe)
    cudaFuncSetAttribute(lstm_kernel,
                         cudaFuncAttributeMaxDynamicSharedMemorySize, HS_BYTES);

    // flag reset must precede the persistent kernel each call (graph replays)
    reset_bar_kernel<<<8, 512>>>();

    dim3 ggrid(G4 / BN, (TT * NB) / BM);        // (16, 256)
    gemm_xh_kernel<<<ggrid, 256>>>(x, Wxh, bxh, bhh);

    lstm_kernel<<<NCTA, 256, HS_BYTES>>>(Whh, y);
}

// round 8
// speedup vs baseline: 1.3456x; 1.3456x over previous
#include <cuda_runtime.h>
#include <cuda_bf16.h>
#include <math.h>

// Problem constants
#define NB   64     // batch
#define TT   512    // time steps
#define DD   512    // input dim
#define HH   512    // hidden dim
#define G4   2048   // 4*H

typedef unsigned long long u64;

// ---------------------------------------------------------------------------
// Packed f32x2 helpers (sm_103a FFMA2 — ptxas never auto-generates these)
// ---------------------------------------------------------------------------
__device__ __forceinline__ u64 pack_dup(float v)
{
    u64 r; asm("mov.b64 %0, {%1, %1};" : "=l"(r) : "f"(v)); return r;
}
__device__ __forceinline__ void ffma2(u64& acc, u64 a, u64 b)
{
    asm("fma.rn.f32x2 %0, %1, %2, %0;" : "+l"(acc) : "l"(a), "l"(b));
}
__device__ __forceinline__ float2 unpk(u64 v)
{
    float2 r; asm("mov.b64 {%0, %1}, %2;" : "=f"(r.x), "=f"(r.y) : "l"(v)); return r;
}

// ---------------------------------------------------------------------------
// Scratch (device globals: the sanctioned no-alloc workaround)
// ---------------------------------------------------------------------------
#define NCTA 128
#define FLAG_STRIDE 32   // 128B between flags -> distinct L2 lines/slices

__device__ float    g_xh[(size_t)TT * NB * G4];   // (T, N, 4H) pre-projected gates
__device__ unsigned g_flag[NCTA * FLAG_STRIDE];   // per-CTA step flags, padded

// ---------------------------------------------------------------------------
// Kernel 1: xh = x @ W_xh + (b_xh + b_hh)   — FFMA2 inner loop (unchanged)
// ---------------------------------------------------------------------------
#define BM 128
#define BN 128
#define BK 8

__global__ __launch_bounds__(256, 2)
void gemm_xh_kernel(const float* __restrict__ x,
                    const float* __restrict__ Wxh,
                    const float* __restrict__ bxh,
                    const float* __restrict__ bhh)
{
    __shared__ float As[BK][BM];   // transposed A tile
    __shared__ float Bs[BK][BN];

    const int tid = threadIdx.x;
    const int bm  = blockIdx.y;
    const int bn  = blockIdx.x;

    const int warp = tid >> 5, lane = tid & 31;
    const int wm = warp >> 1, wn = warp & 1;
    const int tm = lane & 3,  tn = lane >> 2;
    const int m0 = wm * 32 + tm * 8;
    const int n0 = wn * 64 + tn * 8;

    const int ar = tid >> 1;
    const int aq = tid & 1;
    const int gm = bm * BM + ar;            // global row m = t*64+n
    const int t  = gm >> 6;
    const int nn = gm & 63;
    const float* __restrict__ arow = x + ((size_t)nn * TT + t) * DD;

    const int rb = tid >> 5;
    const int cb = (tid & 31) * 4;
    const float* __restrict__ bcol = Wxh + (size_t)bn * BN + cb;

    u64 acc2[8][4];
#pragma unroll
    for (int i = 0; i < 8; i++)
#pragma unroll
        for (int j = 0; j < 4; j++) acc2[i][j] = 0ull;

    for (int k0 = 0; k0 < DD; k0 += BK) {
        const float4 av = *(const float4*)(arow + k0 + aq * 4);
        const float4 bv = *(const float4*)(bcol + (size_t)(k0 + rb) * G4);
        __syncthreads();
        As[aq * 4 + 0][ar] = av.x;
        As[aq * 4 + 1][ar] = av.y;
        As[aq * 4 + 2][ar] = av.z;
        As[aq * 4 + 3][ar] = av.w;
        *(float4*)&Bs[rb][cb] = bv;
        __syncthreads();

#pragma unroll
        for (int kk = 0; kk < BK; kk++) {
            float ra[8];
            *(float4*)&ra[0] = *(const float4*)&As[kk][m0];
            *(float4*)&ra[4] = *(const float4*)&As[kk][m0 + 4];
            const ulonglong2 b01 = *(const ulonglong2*)&Bs[kk][n0];
            const ulonglong2 b23 = *(const ulonglong2*)&Bs[kk][n0 + 4];
#pragma unroll
            for (int i = 0; i < 8; i++) {
                const u64 ai = pack_dup(ra[i]);
                ffma2(acc2[i][0], ai, b01.x);
                ffma2(acc2[i][1], ai, b01.y);
                ffma2(acc2[i][2], ai, b23.x);
                ffma2(acc2[i][3], ai, b23.y);
            }
        }
    }

    const int col0 = bn * BN + n0;
    float bsum[8];
#pragma unroll
    for (int j = 0; j < 8; j++)
        bsum[j] = bxh[col0 + j] + bhh[col0 + j];

#pragma unroll
    for (int i = 0; i < 8; i++) {
        const size_t row = (size_t)(bm * BM + m0 + i);
        float* p = g_xh + row * G4 + col0;
        float2 c0 = unpk(acc2[i][0]);
        float2 c1 = unpk(acc2[i][1]);
        float2 c2 = unpk(acc2[i][2]);
        float2 c3 = unpk(acc2[i][3]);
        float4 v0 = make_float4(c0.x + bsum[0], c0.y + bsum[1],
                                c1.x + bsum[2], c1.y + bsum[3]);
        float4 v1 = make_float4(c2.x + bsum[4], c2.y + bsum[5],
                                c3.x + bsum[6], c3.y + bsum[7]);
        *(float4*)p       = v0;
        *(float4*)(p + 4) = v1;
    }
}

// ---------------------------------------------------------------------------
// Kernel 2: flag reset (keeps graph replays deterministic)
// ---------------------------------------------------------------------------
__global__ void reset_bar_kernel()
{
    const int i = blockIdx.x * blockDim.x + threadIdx.x;
    if (i < NCTA * FLAG_STRIDE) g_flag[i] = 0u;
}

// ---------------------------------------------------------------------------
// Kernel 3: persistent LSTM recurrence — 32 hidden-groups x 4 batch-groups.
// CTA b: bg = b&3 owns batches [bg*16, bg*16+16); hg = b>>2 owns h-cols
// [hg*16, hg*16+16). A batch-group's h is produced AND consumed entirely by
// its own 32 CTAs -> four independent 32-CTA flag barriers (less straggler
// span), and h staging is 32 KB/CTA/step (4 MB/step chip-wide, was 16 MB).
// W_hh slice (512 x 64 gatecols, ~139 KB) lives in smem, slices PERMUTED
// (p = gt*16 + (jj&3)*4 + (jj>>2)) so the 4 distinct per-warp w-LDS
// addresses land at bank offsets 0/4/8/12 -> conflict-free.
// Dot engine: FFMA2, k-paired (13 instr / 4 k), fma-issue-bound.
// c state in registers; h exchanged through y (d_out) in L2.
// ---------------------------------------------------------------------------
#define NBG  16           // batches per batch-group
#define WSL  516          // per-slice stride (512 + 4 floats)
#define HSL  516          // per-h-row stride
#define GSL  68           // gate staging row stride (4 gates * 17)

#define SM_W   (64 * WSL)                 // 33024 floats
#define SM_H   (NBG * HSL)                // 8256
#define SM_G   (NBG * GSL)                // 1088
#define SM_FLOATS (SM_W + SM_H + SM_G)    // 42368
#define SM_BYTES  (SM_FLOATS * 4)         // 169472

__device__ __forceinline__ float sigmoidf_(float v)
{
    return 1.f / (1.f + expf(-v));
}

__global__ __launch_bounds__(256, 1)
void lstm_kernel(const float* __restrict__ Whh, float* __restrict__ y)
{
    extern __shared__ float sm[];
    float* __restrict__ wsT = sm;               // [64 slices][WSL]
    float* __restrict__ hs  = sm + SM_W;        // [NBG][HSL]
    float* __restrict__ gs  = sm + SM_W + SM_H; // [NBG][GSL]

    const int tid  = threadIdx.x;
    const int b    = blockIdx.x;
    const int bg   = b & 3;                // batch group
    const int hg   = b >> 2;               // hidden group
    const int hc0  = hg * 16;              // first h-col owned
    const int nb0  = bg * NBG;             // first batch owned
    const int warp = tid >> 5;
    const int lane = tid & 31;

    // ---- dot-phase mapping: (n_local, c4); gt = warp>>1 constant per warp
    const int n_local = (lane & 7) | ((warp & 1) << 3);     // 0..15
    const int c43     = lane >> 3;                          // 0..3 (= c4&3)
    const int gt      = warp >> 1;                          // 0..3 gate type
    const int jj0     = c43 * 4;                            // first local col

    // ---- load W_hh slices into smem (permuted slice order), one-time
    for (int i = tid; i < 64 * 512; i += 256) {
        const int k  = i & 511;
        const int p  = i >> 9;             // slice position 0..63
        const int pg = p >> 4;             // gate type
        const int ii = (p & 15) >> 2;
        const int pc = p & 3;
        const int jj = pc * 4 + ii;        // local h-col
        wsT[p * WSL + k] = Whh[(size_t)k * G4 + pg * HH + hc0 + jj];
    }

    // w slice base pointers for this thread's 4 columns (i = 0..3)
    const float* __restrict__ wp0 = &wsT[(gt * 16 + 0 * 4 + c43) * WSL];
    const float* __restrict__ wp1 = &wsT[(gt * 16 + 1 * 4 + c43) * WSL];
    const float* __restrict__ wp2 = &wsT[(gt * 16 + 2 * 4 + c43) * WSL];
    const float* __restrict__ wp3 = &wsT[(gt * 16 + 3 * 4 + c43) * WSL];
    const float* __restrict__ hrow = &hs[n_local * HSL];

    // ---- activation-phase mapping: one (n3, j3) output column per thread
    const int n3 = tid >> 4;               // 0..15
    const int j3 = tid & 15;               // 0..15
    float creg = 0.f;                      // c state for (nb0+n3, hc0+j3)

    unsigned* const myflag   = &g_flag[b * FLAG_STRIDE];
    unsigned* const pollflag = &g_flag[(((tid & 31) << 2) | bg) * FLAG_STRIDE];

    __syncthreads();

    for (int tstep = 0; tstep < TT; tstep++) {
        // ---- prefetch this step's input-projection gates (no cross-CTA dep)
        const float4 xv = *(const float4*)(g_xh +
            ((size_t)tstep * NB + nb0 + n_local) * G4 + gt * HH + hc0 + jj0);

        if (tstep > 0) {
            // ---- group barrier wait: our 32 CTAs finished step tstep-1
            if (tid < 32) {
                const unsigned want = (unsigned)tstep;
                unsigned v;
                do {
                    asm volatile("ld.acquire.gpu.u32 %0, [%1];"
                                 : "=r"(v) : "l"(pollflag) : "memory");
                } while (v < want);
            }
            __syncthreads();

            // ---- stage h(t-1) for our 16 batches: warp copies 2 rows
            const size_t tb = (size_t)(tstep - 1) * HH;
#pragma unroll
            for (int r2 = 0; r2 < 2; r2++) {
                const int row = warp * 2 + r2;
                const float4* __restrict__ src =
                    (const float4*)(y + (size_t)(nb0 + row) * TT * HH + tb);
                float4* __restrict__ dst = (float4*)&hs[row * HSL];
#pragma unroll
                for (int p = 0; p < 4; p++)
                    dst[lane + p * 32] = src[lane + p * 32];
            }
        }
        __syncthreads();

        // ---- dot: 4 gate columns (gt, jj0..jj0+3) for batch n_local
        u64 acc0 = 0ull, acc1 = 0ull, acc2v = 0ull, acc3 = 0ull;
        if (tstep > 0) {
#pragma unroll 8
            for (int k = 0; k < HH; k += 4) {
                const ulonglong2 hp = *(const ulonglong2*)(hrow + k);
                const ulonglong2 w0 = *(const ulonglong2*)(wp0 + k);
                const ulonglong2 w1 = *(const ulonglong2*)(wp1 + k);
                const ulonglong2 w2 = *(const ulonglong2*)(wp2 + k);
                const ulonglong2 w3 = *(const ulonglong2*)(wp3 + k);
                ffma2(acc0, hp.x, w0.x); ffma2(acc0, hp.y, w0.y);
                ffma2(acc1, hp.x, w1.x); ffma2(acc1, hp.y, w1.y);
                ffma2(acc2v, hp.x, w2.x); ffma2(acc2v, hp.y, w2.y);
                ffma2(acc3, hp.x, w3.x); ffma2(acc3, hp.y, w3.y);
            }
        }

        // horizontal pair-reduce + prefetched input gates
        {
            const float2 s0 = unpk(acc0), s1 = unpk(acc1);
            const float2 s2 = unpk(acc2v), s3 = unpk(acc3);
            float* g = &gs[n_local * GSL + gt * 17 + jj0];
            g[0] = s0.x + s0.y + xv.x;
            g[1] = s1.x + s1.y + xv.y;
            g[2] = s2.x + s2.y + xv.z;
            g[3] = s3.x + s3.y + xv.w;
        }
        __syncthreads();

        // ---- activations: one output column per thread
        {
            const float* g = &gs[n3 * GSL];
            const float gi = g[0  + j3];
            const float gf = g[17 + j3];
            const float gc = g[34 + j3];
            const float go = g[51 + j3];
            const float iv = sigmoidf_(gi);
            const float fv = sigmoidf_(gf);
            const float gv = tanhf(gc);
            const float ov = sigmoidf_(go);
            creg = fv * creg + iv * gv;
            const float hv = ov * tanhf(creg);
            y[(size_t)(nb0 + n3) * TT * HH + (size_t)tstep * HH + hc0 + j3] = hv;
        }
        __syncthreads();   // all y stores done before the release below

        if (tstep < TT - 1) {
            // ---- group barrier arrive: one release store, own slot
            if (tid == 0) {
                asm volatile("st.release.gpu.u32 [%0], %1;"
                             :: "l"(myflag), "r"((unsigned)(tstep + 1))
                             : "memory");
            }
        }
    }
}

// ---------------------------------------------------------------------------
// Launch
// ---------------------------------------------------------------------------
extern "C" void kernel_launch(void* const* d_in, const int* in_sizes, int n_in,
                              void* d_out, int out_size)
{
    const float* x   = (const float*)d_in[0];   // (64, 512, 512)
    const float* Wxh = (const float*)d_in[1];   // (512, 2048)
    const float* Whh = (const float*)d_in[2];   // (512, 2048)
    const float* bxh = (const float*)d_in[3];   // (2048,)
    const float* bhh = (const float*)d_in[4];   // (2048,)
    float* y = (float*)d_out;                   // (64, 512, 512)

    // opt-in to >48KB dynamic smem (idempotent host call, capture-safe)
    cudaFuncSetAttribute(lstm_kernel,
                         cudaFuncAttributeMaxDynamicSharedMemorySize, SM_BYTES);

    // flag reset must precede the persistent kernel each call (graph replays)
    reset_bar_kernel<<<8, 512>>>();

    dim3 ggrid(G4 / BN, (TT * NB) / BM);        // (16, 256)
    gemm_xh_kernel<<<ggrid, 256>>>(x, Wxh, bxh, bhh);

    lstm_kernel<<<NCTA, 256, SM_BYTES>>>(Whh, y);
}